// round 4
// baseline (speedup 1.0000x reference)
#include <cuda_runtime.h>
#include <math.h>

// Scratch (allocation-free).
__device__ float g_hp[8192];          // [bc][p]           h-bin means
__device__ float g_vp_part[131072];   // [bc][p][q]        per-h-bin w partial sums
__device__ float g_sig[131072];       // [bc][p][q]        precomputed sigmoids

// ---------------------------------------------------------------------------
// Kernel 1: strip pooling. One block per (plane, h-bin): grid 8192, 128 thr.
// Block (bc,p) reads rows [16p,16p+16) of plane bc (16KB). It fully owns
// h-bin p (writes g_hp directly) and produces 16 w-bin partials into
// g_vp_part[bc][p][*] (summed over p in the mix kernel - no atomics/zeroing).
// Thread t: cg = t&63 (float4 column, one w-bin = cg>>2), rows half*8..+8.
// ---------------------------------------------------------------------------
__global__ void __launch_bounds__(128) sp_pool_kernel(const float* __restrict__ x) {
    const int blk = blockIdx.x;           // 0..8191
    const int bc  = blk >> 4;
    const int p   = blk & 15;
    const float4* __restrict__ tile =
        reinterpret_cast<const float4*>(x + (size_t)bc * 65536) + p * 1024;

    const int t    = threadIdx.x;
    const int half = t >> 6;              // 0..1 (row half)
    const int cg   = t & 63;
    const int lane = t & 31;
    const int wrp  = t >> 5;              // warp 0..3

    // 8 independent loads, front-batched.
    float4 v[8];
#pragma unroll
    for (int j = 0; j < 8; ++j)
        v[j] = tile[(half * 8 + j) * 64 + cg];

    float acc = 0.f;
#pragma unroll
    for (int j = 0; j < 8; ++j)
        acc += (v[j].x + v[j].y) + (v[j].z + v[j].w);

    __shared__ float s_h[4];
    __shared__ float s_w[16];
    if (t < 16) s_w[t] = 0.f;
    __syncthreads();

    // w-bin partial: 4 consecutive lanes share w-bin (cg>>2). Two warps
    // (same cg range, different row half) hit the same shared slot.
    float wsum = acc;
    wsum += __shfl_down_sync(0xffffffffu, wsum, 2);
    wsum += __shfl_down_sync(0xffffffffu, wsum, 1);
    if ((lane & 3) == 0) atomicAdd(&s_w[cg >> 2], wsum);

    // h-bin: block-wide sum of acc.
    float hsum = acc;
#pragma unroll
    for (int off = 16; off; off >>= 1)
        hsum += __shfl_down_sync(0xffffffffu, hsum, off);
    if (lane == 0) s_h[wrp] = hsum;
    __syncthreads();

    if (t == 0)
        g_hp[bc * 16 + p] = (s_h[0] + s_h[1] + s_h[2] + s_h[3]) * (1.0f / 4096.0f);
    if (t < 16)
        g_vp_part[bc * 256 + p * 16 + t] = s_w[t];
}

// ---------------------------------------------------------------------------
// Kernel 2: tiny linear + BN chain + sigmoid table. One block per batch.
// ---------------------------------------------------------------------------
__global__ void __launch_bounds__(256) sp_mix_kernel(
    const float* __restrict__ Wh, const float* __restrict__ bh,
    const float* __restrict__ Wv, const float* __restrict__ bv,
    const float* __restrict__ Wf, const float* __restrict__ bf,
    const float* __restrict__ hg, const float* __restrict__ hb,
    const float* __restrict__ hm, const float* __restrict__ hv,
    const float* __restrict__ vg, const float* __restrict__ vb,
    const float* __restrict__ vm, const float* __restrict__ vv,
    const float* __restrict__ fg, const float* __restrict__ fb,
    const float* __restrict__ fm, const float* __restrict__ fvr)
{
    __shared__ float s_hp[1024];   // [c][p]
    __shared__ float s_vp[1024];   // [c][q]
    __shared__ float s_hpn[1024];
    __shared__ float s_vpn[1024];
    __shared__ float s_fh[1024];   // [c][p]
    __shared__ float s_fv[1024];   // [c][q]

    const int b   = blockIdx.x;
    const int tid = threadIdx.x;

    for (int i = tid; i < 1024; i += 256) {
        s_hp[i] = g_hp[b * 1024 + i];
        const int c = i >> 4;
        const int q = i & 15;
        float sum = 0.f;
        const float* vp = g_vp_part + (size_t)(b * 64 + c) * 256 + q;
#pragma unroll
        for (int pp = 0; pp < 16; ++pp) sum += vp[pp * 16];
        s_vp[i] = sum * (1.0f / 4096.0f);
    }
    __syncthreads();

    for (int i = tid; i < 1024; i += 256) {
        const int o = i >> 4;
        const int p = i & 15;
        float ah = 0.f, av = 0.f;
#pragma unroll 8
        for (int c = 0; c < 64; ++c) {
            ah += Wh[o * 64 + c] * s_hp[c * 16 + p];
            av += Wv[o * 64 + c] * s_vp[c * 16 + p];
        }
        const float invh = hg[o] * rsqrtf(hv[o] + 1e-5f);
        const float invv = vg[o] * rsqrtf(vv[o] + 1e-5f);
        s_hpn[i] = (ah + bh[o]) * invh + (hb[o] - hm[o] * invh);
        s_vpn[i] = (av + bv[o]) * invv + (vb[o] - vm[o] * invv);
    }
    __syncthreads();

    for (int i = tid; i < 1024; i += 256) {
        const int o = i >> 4;
        const int p = i & 15;
        float ah = 0.f, av = 0.f;
#pragma unroll 8
        for (int c = 0; c < 64; ++c) {
            ah += Wf[o * 128 + c]      * s_hpn[c * 16 + p];
            av += Wf[o * 128 + 64 + c] * s_vpn[c * 16 + p];
        }
        const float invf = fg[o] * rsqrtf(fvr[o] + 1e-5f);
        s_fh[i] = ah * invf;
        s_fv[i] = (av + bf[o]) * invf + (fb[o] - fm[o] * invf);
    }
    __syncthreads();

    // sigmoid table: 64 channels x 16 x 16 per batch = 16384 values.
    for (int i = tid; i < 16384; i += 256) {
        const int c = i >> 8;
        const int p = (i >> 4) & 15;
        const int q = i & 15;
        const float z = s_fh[c * 16 + p] + s_fv[c * 16 + q];
        g_sig[(size_t)(b * 64 + c) * 256 + p * 16 + q] = 1.0f / (1.0f + expf(-z));
    }
}

// ---------------------------------------------------------------------------
// Kernel 3: out = sig[bc, h>>4, w>>4] * x. One block per 32-row chunk
// (grid 4096). All 8 float4 loads issued before any store (forced MLP=8).
// Reverse order + .cs to exploit/preserve pool-era L2 residency of x.
// ---------------------------------------------------------------------------
__global__ void __launch_bounds__(256) sp_gate_kernel(
    const float4* __restrict__ x4, float4* __restrict__ out4)
{
    const int rblk  = 4095 - blockIdx.x;
    const int plane = rblk >> 3;
    const int chunk = rblk & 7;
    const size_t base = (size_t)plane * 16384 + (size_t)chunk * 2048;

    const int t  = threadIdx.x;
    const int wb = (t & 63) >> 2;

    const float* __restrict__ sig = g_sig + plane * 256 + chunk * 32;
    const float s0 = __ldg(&sig[wb]);
    const float s1 = __ldg(&sig[16 + wb]);

    float4 v[8];
#pragma unroll
    for (int j = 0; j < 8; ++j)
        v[j] = __ldcs(&x4[base + j * 256 + t]);

#pragma unroll
    for (int j = 0; j < 8; ++j) {
        const float s = (j < 4) ? s0 : s1;
        float4 o = v[j];
        o.x *= s; o.y *= s; o.z *= s; o.w *= s;
        __stcs(&out4[base + j * 256 + t], o);
    }
}

// ---------------------------------------------------------------------------
extern "C" void kernel_launch(void* const* d_in, const int* in_sizes, int n_in,
                              void* d_out, int out_size)
{
    const float* x  = (const float*)d_in[0];
    const float* Wh = (const float*)d_in[1];
    const float* bh = (const float*)d_in[2];
    const float* Wv = (const float*)d_in[3];
    const float* bv = (const float*)d_in[4];
    const float* Wf = (const float*)d_in[5];
    const float* bf = (const float*)d_in[6];
    const float* hg = (const float*)d_in[7];
    const float* hb = (const float*)d_in[8];
    const float* hm = (const float*)d_in[9];
    const float* hv = (const float*)d_in[10];
    const float* vg = (const float*)d_in[11];
    const float* vb = (const float*)d_in[12];
    const float* vm = (const float*)d_in[13];
    const float* vv = (const float*)d_in[14];
    const float* fg = (const float*)d_in[15];
    const float* fb = (const float*)d_in[16];
    const float* fm = (const float*)d_in[17];
    const float* fv = (const float*)d_in[18];

    sp_pool_kernel<<<8192, 128>>>(x);
    sp_mix_kernel<<<8, 256>>>(Wh, bh, Wv, bv, Wf, bf,
                              hg, hb, hm, hv,
                              vg, vb, vm, vv,
                              fg, fb, fm, fv);
    sp_gate_kernel<<<4096, 256>>>((const float4*)x, (float4*)d_out);
}